// round 8
// baseline (speedup 1.0000x reference)
#include <cuda_runtime.h>
#include <cuda_fp16.h>
#include <math.h>
#include <stdint.h>

#define Bn   16384
#define TOK  128          // tokens per CTA (8 batches x 16)
#define LDH  72           // half stride (144B rows -> conflict-free ldmatrix/stmatrix)
#define LDF  68           // float stride for x2 buffer
#define NTH  256
#define EPSV 1e-5f
#define SCL  0.25f
#define MATH 4608         // 64*LDH halves per packed 64x64 matrix

// Packed fp16 weights: 16 head mats (Wq,Wk,Wv,Wp per head) + 4 W1 chunks + 4 W2 chunks
__device__ __align__(16) __half gWpack[24 * MATH];

// ---------------- PTX helpers ----------------
__device__ __forceinline__ uint32_t cvta_s(const void* p) {
    return (uint32_t)__cvta_generic_to_shared(p);
}
__device__ __forceinline__ void ldsm_x4(uint32_t* r, uint32_t a) {
    asm volatile("ldmatrix.sync.aligned.m8n8.x4.shared.b16 {%0,%1,%2,%3}, [%4];"
                 : "=r"(r[0]), "=r"(r[1]), "=r"(r[2]), "=r"(r[3]) : "r"(a));
}
__device__ __forceinline__ void ldsm_x4_t(uint32_t* r, uint32_t a) {
    asm volatile("ldmatrix.sync.aligned.m8n8.x4.trans.shared.b16 {%0,%1,%2,%3}, [%4];"
                 : "=r"(r[0]), "=r"(r[1]), "=r"(r[2]), "=r"(r[3]) : "r"(a));
}
__device__ __forceinline__ void stsm_x4(uint32_t a, uint32_t r0, uint32_t r1,
                                        uint32_t r2, uint32_t r3) {
    asm volatile("stmatrix.sync.aligned.m8n8.x4.shared.b16 [%0], {%1,%2,%3,%4};"
                 :: "r"(a), "r"(r0), "r"(r1), "r"(r2), "r"(r3) : "memory");
}
__device__ __forceinline__ void mma16816(float* d, const uint32_t* a, const uint32_t* b) {
    asm volatile("mma.sync.aligned.m16n8k16.row.col.f32.f16.f16.f32 "
                 "{%0,%1,%2,%3},{%4,%5,%6,%7},{%8,%9},{%0,%1,%2,%3};"
                 : "+f"(d[0]), "+f"(d[1]), "+f"(d[2]), "+f"(d[3])
                 : "r"(a[0]), "r"(a[1]), "r"(a[2]), "r"(a[3]), "r"(b[0]), "r"(b[1]));
}
__device__ __forceinline__ uint32_t h2u(float a, float b) {
    __half2 h = __floats2half2_rn(a, b);
    return *(uint32_t*)&h;
}
__device__ __forceinline__ void cp_commit() { asm volatile("cp.async.commit_group;"); }
__device__ __forceinline__ void cp_wait0()  { asm volatile("cp.async.wait_group 0;"); }
__device__ __forceinline__ void cp_wait1()  { asm volatile("cp.async.wait_group 1;"); }
__device__ __forceinline__ void copy_async(__half* dst, const __half* src, int bytes, int tid) {
    uint32_t d = cvta_s(dst);
    const char* s = (const char*)src;
    for (int off = tid * 16; off < bytes; off += NTH * 16)
        asm volatile("cp.async.cg.shared.global [%0], [%1], 16;" :: "r"(d + off), "l"(s + off));
}

// ---------------- A-fragment cache + register-A GEMM ----------------
__device__ __forceinline__ void load_afrag(const __half* A, int mr0, int offA, uint32_t af[4][8]) {
    uint32_t aB = cvta_s(A);
#pragma unroll
    for (int i = 0; i < 4; ++i) {
        ldsm_x4(&af[i][0], aB + 2u * (uint32_t)(mr0 * LDH + i * 16 + offA));
        ldsm_x4(&af[i][4], aB + 2u * (uint32_t)((mr0 + 16) * LDH + i * 16 + offA));
    }
}
__device__ __forceinline__ void wgemm_rf(const uint32_t af[4][8], const __half* B,
                                         int nc0, int offA, float acc[2][4][4]) {
    uint32_t bB = cvta_s(B);
#pragma unroll
    for (int i = 0; i < 4; ++i) {
        uint32_t b0[4], b1[4];
        ldsm_x4_t(b0, bB + 2u * (uint32_t)(i * 16 * LDH + nc0 + offA));
        ldsm_x4_t(b1, bB + 2u * (uint32_t)(i * 16 * LDH + nc0 + 16 + offA));
#pragma unroll
        for (int mi = 0; mi < 2; ++mi) {
            const uint32_t* aa = &af[i][mi * 4];
            mma16816(acc[mi][0], aa, b0);
            mma16816(acc[mi][1], aa, b0 + 2);
            mma16816(acc[mi][2], aa, b1);
            mma16816(acc[mi][3], aa, b1 + 2);
        }
    }
}
__device__ __forceinline__ void wgemm(const __half* A, const __half* B,
                                      int mr0, int nc0, int offA, float acc[2][4][4]) {
    uint32_t af[4][8];
    load_afrag(A, mr0, offA, af);
    wgemm_rf(af, B, nc0, offA, acc);
}

__device__ __forceinline__ void init_bias(float acc[2][4][4], const float* bias,
                                          int nc0, int lane) {
    int c2 = 2 * (lane & 3);
#pragma unroll
    for (int j = 0; j < 4; ++j) {
        float2 bv = *(const float2*)(bias + nc0 + 8 * j + c2);
#pragma unroll
        for (int mi = 0; mi < 2; ++mi) {
            acc[mi][j][0] = bv.x; acc[mi][j][1] = bv.y;
            acc[mi][j][2] = bv.x; acc[mi][j][3] = bv.y;
        }
    }
}

// fragment-layout epilogue: fp32 acc -> (opt relu) -> half -> smem via stmatrix
__device__ __forceinline__ void store_half_tile(__half* C, int mr0, int nc0, int lane,
                                                const float acc[2][4][4], bool relu) {
    const uint32_t base = cvta_s(C);
    const int rowoff = ((lane >> 3) & 1) * 8 + (lane & 7);
    const int colsel = lane >> 4;              // 0 or 1 -> which 8-col block
#pragma unroll
    for (int mi = 0; mi < 2; ++mi) {
#pragma unroll
        for (int jj = 0; jj < 2; ++jj) {
            const int j0 = 2 * jj, j1 = 2 * jj + 1;
            float v0 = acc[mi][j0][0], v1 = acc[mi][j0][1];
            float v2 = acc[mi][j0][2], v3 = acc[mi][j0][3];
            float v4 = acc[mi][j1][0], v5 = acc[mi][j1][1];
            float v6 = acc[mi][j1][2], v7 = acc[mi][j1][3];
            if (relu) {
                v0 = fmaxf(v0, 0.f); v1 = fmaxf(v1, 0.f);
                v2 = fmaxf(v2, 0.f); v3 = fmaxf(v3, 0.f);
                v4 = fmaxf(v4, 0.f); v5 = fmaxf(v5, 0.f);
                v6 = fmaxf(v6, 0.f); v7 = fmaxf(v7, 0.f);
            }
            uint32_t addr = base + 2u * (uint32_t)((mr0 + 16 * mi + rowoff) * LDH
                                                   + nc0 + 8 * (j0 + colsel));
            stsm_x4(addr, h2u(v0, v1), h2u(v2, v3), h2u(v4, v5), h2u(v6, v7));
        }
    }
}

// LayerNorm 64-wide rows (2 threads/row), fp32 src -> half dst (stride LDH)
__device__ __forceinline__ void layernorm_half(const float* __restrict__ src, int sstride,
                                               const float* __restrict__ g,
                                               const float* __restrict__ bb,
                                               __half* dst, int tid) {
    int r = tid >> 1, hf = tid & 1;
    const float* sp = src + r * sstride + hf * 32;
    float4 v[8];
#pragma unroll
    for (int i = 0; i < 8; ++i) v[i] = *(const float4*)(sp + i * 4);
    float s = 0.f, ss = 0.f;
#pragma unroll
    for (int i = 0; i < 8; ++i) {
        s  += v[i].x + v[i].y + v[i].z + v[i].w;
        ss += v[i].x * v[i].x + v[i].y * v[i].y + v[i].z * v[i].z + v[i].w * v[i].w;
    }
    s  += __shfl_xor_sync(0xffffffffu, s, 1);
    ss += __shfl_xor_sync(0xffffffffu, ss, 1);
    float mean = s * (1.f / 64.f);
    float inv  = rsqrtf(ss * (1.f / 64.f) - mean * mean + EPSV);
    __half* dp = dst + r * LDH + hf * 32;
#pragma unroll
    for (int i = 0; i < 8; ++i) {
        int d = hf * 32 + i * 4;
        float o0 = (v[i].x - mean) * inv * __ldg(g + d + 0) + __ldg(bb + d + 0);
        float o1 = (v[i].y - mean) * inv * __ldg(g + d + 1) + __ldg(bb + d + 1);
        float o2 = (v[i].z - mean) * inv * __ldg(g + d + 2) + __ldg(bb + d + 2);
        float o3 = (v[i].w - mean) * inv * __ldg(g + d + 3) + __ldg(bb + d + 3);
        *(__half2*)(dp + i * 4)     = __floats2half2_rn(o0, o1);
        *(__half2*)(dp + i * 4 + 2) = __floats2half2_rn(o2, o3);
    }
}

// per-warp causal attention for one batch (16x16); ctx written back via stmatrix
__device__ __forceinline__ void attention_warp(__half* sQ, const __half* sK, const __half* sV,
                                               int w, int lane, int offA, int offK) {
    const int base = w * 16;
    uint32_t qB = cvta_s(sQ), kB = cvta_s(sK), vB = cvta_s(sV);

    float s0[4] = {0.f, 0.f, 0.f, 0.f};
    float s1[4] = {0.f, 0.f, 0.f, 0.f};
#pragma unroll
    for (int k0 = 0; k0 < 64; k0 += 16) {
        uint32_t aq[4], kb[4];
        ldsm_x4(aq, qB + 2u * (uint32_t)(base * LDH + k0 + offA));
        ldsm_x4(kb, kB + 2u * (uint32_t)(base * LDH + k0 + offK));
        mma16816(s0, aq, kb);
        mma16816(s1, aq, kb + 2);
    }
    const int r = lane >> 2, c2 = 2 * (lane & 3);

    float sc[2][4];
#pragma unroll
    for (int t = 0; t < 2; ++t) {
        const float* sv_ = t ? s1 : s0;
#pragma unroll
        for (int q = 0; q < 4; ++q) {
            int row = r + ((q >> 1) * 8);
            int col = 8 * t + c2 + (q & 1);
            sc[t][q] = (col <= row) ? sv_[q] * SCL : -1e30f;
        }
    }
    float m0 = fmaxf(fmaxf(sc[0][0], sc[0][1]), fmaxf(sc[1][0], sc[1][1]));
    float m1 = fmaxf(fmaxf(sc[0][2], sc[0][3]), fmaxf(sc[1][2], sc[1][3]));
    m0 = fmaxf(m0, __shfl_xor_sync(0xffffffffu, m0, 1));
    m0 = fmaxf(m0, __shfl_xor_sync(0xffffffffu, m0, 2));
    m1 = fmaxf(m1, __shfl_xor_sync(0xffffffffu, m1, 1));
    m1 = fmaxf(m1, __shfl_xor_sync(0xffffffffu, m1, 2));
    float p[2][4];
    float sum0 = 0.f, sum1 = 0.f;
#pragma unroll
    for (int t = 0; t < 2; ++t) {
        p[t][0] = __expf(sc[t][0] - m0); p[t][1] = __expf(sc[t][1] - m0);
        p[t][2] = __expf(sc[t][2] - m1); p[t][3] = __expf(sc[t][3] - m1);
        sum0 += p[t][0] + p[t][1];
        sum1 += p[t][2] + p[t][3];
    }
    sum0 += __shfl_xor_sync(0xffffffffu, sum0, 1);
    sum0 += __shfl_xor_sync(0xffffffffu, sum0, 2);
    sum1 += __shfl_xor_sync(0xffffffffu, sum1, 1);
    sum1 += __shfl_xor_sync(0xffffffffu, sum1, 2);
    float i0 = 1.f / sum0, i1 = 1.f / sum1;

    uint32_t aP[4];
    aP[0] = h2u(p[0][0] * i0, p[0][1] * i0);
    aP[1] = h2u(p[0][2] * i1, p[0][3] * i1);
    aP[2] = h2u(p[1][0] * i0, p[1][1] * i0);
    aP[3] = h2u(p[1][2] * i1, p[1][3] * i1);

    // ctx = P @ V -> overwrite sQ rows of this batch (stmatrix epilogue)
    const int rowoff = ((lane >> 3) & 1) * 8 + (lane & 7);
    const int colsel = lane >> 4;
    const uint32_t cbase = qB + 2u * (uint32_t)((base + rowoff) * LDH + colsel * 8);
#pragma unroll
    for (int d0 = 0; d0 < 64; d0 += 16) {
        uint32_t vb[4];
        ldsm_x4_t(vb, vB + 2u * (uint32_t)(base * LDH + d0 + offA));
        float c0f[4] = {0.f, 0.f, 0.f, 0.f};
        float c1f[4] = {0.f, 0.f, 0.f, 0.f};
        mma16816(c0f, aP, vb);
        mma16816(c1f, aP, vb + 2);
        stsm_x4(cbase + 2u * (uint32_t)d0,
                h2u(c0f[0], c0f[1]), h2u(c0f[2], c0f[3]),
                h2u(c1f[0], c1f[1]), h2u(c1f[2], c1f[3]));
    }
}

// ---------------- weight pack pre-kernel ----------------
__global__ void pack_weights(const float* __restrict__ Wq, const float* __restrict__ Wk,
                             const float* __restrict__ Wv, const float* __restrict__ Wp,
                             const float* __restrict__ W1, const float* __restrict__ W2) {
    int m = blockIdx.x, tid = threadIdx.x;
    const float* base;
    int stride;
    if (m < 16) {
        int h = m >> 2, t = m & 3;
        const float* w = (t == 0) ? Wq : (t == 1) ? Wk : (t == 2) ? Wv : Wp;
        base = w + h * 4096; stride = 64;
    } else if (m < 20) {
        base = W1 + (m - 16) * 64; stride = 256;   // W1[:, cc*64 .. +63]
    } else {
        base = W2 + (m - 20) * 4096; stride = 64;  // W2[cc*64 .. +63, :]
    }
    __half* dst = gWpack + m * MATH;
#pragma unroll
    for (int j = 0; j < 4; ++j) {
        int e = tid + j * 256;          // float4 unit 0..1023
        int k = e >> 4, c4 = (e & 15) * 4;
        float4 v = *(const float4*)(base + k * stride + c4);
        *(__half2*)(dst + k * LDH + c4)     = __floats2half2_rn(v.x, v.y);
        *(__half2*)(dst + k * LDH + c4 + 2) = __floats2half2_rn(v.z, v.w);
    }
}

// ---------------- main fused kernel ----------------
__global__ void __launch_bounds__(NTH, 2)
tblock_kernel(const float* __restrict__ x,
              const float* __restrict__ bq, const float* __restrict__ bk,
              const float* __restrict__ bv, const float* __restrict__ bp,
              const float* __restrict__ b1, const float* __restrict__ b2,
              const float* __restrict__ g1, const float* __restrict__ be1,
              const float* __restrict__ g2, const float* __restrict__ be2,
              float* __restrict__ out) {
    extern __shared__ __align__(16) char smraw[];
    __half* sH = (__half*)smraw;       // 128 x LDH
    __half* sQ = sH + TOK * LDH;
    __half* sK = sQ + TOK * LDH;
    __half* sV = sK + TOK * LDH;
    __half* sW = sV + TOK * LDH;       // 4 weight slots x MATH
    float*  x2 = (float*)sK;           // aliased: sK+sV dead after attention phase

    const int tid  = threadIdx.x;
    const int lane = tid & 31;
    const int w    = tid >> 5;
    const int g0   = blockIdx.x * TOK;

    const int mr0 = (w >> 1) * 32, nc0 = (w & 1) * 32;
    const int offA = (((lane >> 3) & 1) * 8 + (lane & 7)) * LDH + (lane >> 4) * 8;
    const int offK = ((lane >> 4) * 8 + (lane & 7)) * LDH + ((lane >> 3) & 1) * 8;

    // prefetch head-0 weights as TWO groups: G_A = Wq/Wk/Wv (slots 0-2), G_B = Wp (slot 3)
    copy_async(sW, gWpack, 3 * MATH * 2, tid);
    cp_commit();
    copy_async(sW + 3 * MATH, gWpack + 3 * MATH, MATH * 2, tid);
    cp_commit();

    // LN1: x -> sH (half)  (overlaps weight copies)
    layernorm_half(x + (size_t)g0 * 64, 64, g1, be1, sH, tid);
    cp_wait1();          // G_A(0) done; G_B(0) may still be in flight
    __syncthreads();

    // cache A fragments of sH (reused for all 12 QKV GEMMs)
    uint32_t ah[4][8];
    load_afrag(sH, mr0, offA, ah);

    float pacc[2][4][4];
    init_bias(pacc, bp, nc0, lane);

#pragma unroll 1
    for (int h = 0; h < 4; ++h) {
        // QKV from cached A frags (slots 0-2 resident & published)
        {
            float acc[2][4][4];
            init_bias(acc, bq + h * 64, nc0, lane);
            wgemm_rf(ah, sW, nc0, offA, acc);
            store_half_tile(sQ, mr0, nc0, lane, acc, false);
        }
        {
            float acc[2][4][4];
            init_bias(acc, bk + h * 64, nc0, lane);
            wgemm_rf(ah, sW + MATH, nc0, offA, acc);
            store_half_tile(sK, mr0, nc0, lane, acc, false);
        }
        {
            float acc[2][4][4];
            init_bias(acc, bv + h * 64, nc0, lane);
            wgemm_rf(ah, sW + 2 * MATH, nc0, offA, acc);
            store_half_tile(sV, mr0, nc0, lane, acc, false);
        }
        __syncthreads();   // QKV reads of slots 0-2 done; QKV stores published

        // G_A(h+1): slots 0-2 now dead -> prefetch next head's Wq/Wk/Wv
        if (h < 3) {
            copy_async(sW, gWpack + (h + 1) * 4 * MATH, 3 * MATH * 2, tid);
            cp_commit();
        }

        attention_warp(sQ, sK, sV, w, lane, offA, offK);

        cp_wait1();        // G_B(h) (slot 3 = Wp_h) done; G_A(h+1) may be in flight
        __syncthreads();   // publish slot 3 + order attention ctx stores before proj

        // pacc += ctx_h @ Wp_h
        wgemm(sQ, sW + 3 * MATH, mr0, nc0, offA, pacc);
        __syncthreads();   // proj reads of slot 3 + sQ done

        // G_B(h+1): slot 3 dead -> prefetch next head's Wp
        if (h < 3) {
            copy_async(sW + 3 * MATH, gWpack + (h + 1) * 4 * MATH + 3 * MATH, MATH * 2, tid);
            cp_commit();
            cp_wait1();      // G_A(h+1) done (G_B(h+1) may remain in flight)
            __syncthreads(); // publish slots 0-2 for next head's QKV
        }
    }

    // x2 = x + attn_out (fp32, aliased over sK/sV — safe: post-proj sync done)
    {
        const int r = lane >> 2, c2 = 2 * (lane & 3);
#pragma unroll
        for (int mi = 0; mi < 2; ++mi)
#pragma unroll
            for (int j = 0; j < 4; ++j) {
                int row = mr0 + 16 * mi + r, col = nc0 + 8 * j + c2;
                float2 xa = *(const float2*)(x + (size_t)(g0 + row) * 64 + col);
                float2 xb = *(const float2*)(x + (size_t)(g0 + row + 8) * 64 + col);
                x2[row * LDF + col]           = xa.x + pacc[mi][j][0];
                x2[row * LDF + col + 1]       = xa.y + pacc[mi][j][1];
                x2[(row + 8) * LDF + col]     = xb.x + pacc[mi][j][2];
                x2[(row + 8) * LDF + col + 1] = xb.y + pacc[mi][j][3];
            }
    }
    // prefetch FFN chunk 0 into slots 0,1 (overlaps x2 + LN2)
    copy_async(sW, gWpack + 16 * MATH, MATH * 2, tid);
    copy_async(sW + MATH, gWpack + 20 * MATH, MATH * 2, tid);
    cp_commit();
    __syncthreads();

    // LN2: x2 -> sH (half)
    layernorm_half(x2, LDF, g2, be2, sH, tid);
    __syncthreads();

    uint32_t ahf[4][8];
    load_afrag(sH, mr0, offA, ahf);

    float oacc[2][4][4];
    init_bias(oacc, b2, nc0, lane);

#pragma unroll 1
    for (int cc = 0; cc < 4; ++cc) {
        const __half* Wb = sW + (cc & 1) * 2 * MATH;   // slots {0,1} or {2,3}
        cp_wait0();
        __syncthreads();   // publish this chunk's weights; orders sQ overwrite below

        // hidden = relu(h2 @ W1c + b1c) -> sQ
        {
            float acc[2][4][4];
            init_bias(acc, b1 + cc * 64, nc0, lane);
            wgemm_rf(ahf, Wb, nc0, offA, acc);
            store_half_tile(sQ, mr0, nc0, lane, acc, true);
        }
        __syncthreads();   // hidden stores published for W2 gemm

        if (cc < 3) {
            __half* nb = sW + ((cc + 1) & 1) * 2 * MATH;
            copy_async(nb, gWpack + (16 + cc + 1) * MATH, MATH * 2, tid);
            copy_async(nb + MATH, gWpack + (20 + cc + 1) * MATH, MATH * 2, tid);
            cp_commit();
        }

        // oacc += hidden @ W2c  (no trailing sync: next iter's top sync orders sQ reuse)
        wgemm(sQ, Wb + MATH, mr0, nc0, offA, oacc);
    }

    // out = x2 + ffn  (x2 re-read by the same threads that wrote it: no sync needed)
    {
        const int r = lane >> 2, c2 = 2 * (lane & 3);
#pragma unroll
        for (int mi = 0; mi < 2; ++mi)
#pragma unroll
            for (int j = 0; j < 4; ++j) {
                int row = mr0 + 16 * mi + r, col = nc0 + 8 * j + c2;
                float2 o0, o1;
                o0.x = x2[row * LDF + col]           + oacc[mi][j][0];
                o0.y = x2[row * LDF + col + 1]       + oacc[mi][j][1];
                o1.x = x2[(row + 8) * LDF + col]     + oacc[mi][j][2];
                o1.y = x2[(row + 8) * LDF + col + 1] + oacc[mi][j][3];
                *(float2*)(out + (size_t)(g0 + row) * 64 + col)     = o0;
                *(float2*)(out + (size_t)(g0 + row + 8) * 64 + col) = o1;
            }
    }
}

extern "C" void kernel_launch(void* const* d_in, const int* in_sizes, int n_in,
                              void* d_out, int out_size) {
    const float* x   = (const float*)d_in[0];
    const float* Wq  = (const float*)d_in[1];
    const float* bq  = (const float*)d_in[2];
    const float* Wk  = (const float*)d_in[3];
    const float* bk  = (const float*)d_in[4];
    const float* Wv  = (const float*)d_in[5];
    const float* bv  = (const float*)d_in[6];
    const float* Wp  = (const float*)d_in[7];
    const float* bp  = (const float*)d_in[8];
    const float* W1  = (const float*)d_in[9];
    const float* b1  = (const float*)d_in[10];
    const float* W2  = (const float*)d_in[11];
    const float* b2  = (const float*)d_in[12];
    const float* g1  = (const float*)d_in[13];
    const float* be1 = (const float*)d_in[14];
    const float* g2  = (const float*)d_in[15];
    const float* be2 = (const float*)d_in[16];
    float* out = (float*)d_out;

    pack_weights<<<24, 256>>>(Wq, Wk, Wv, Wp, W1, W2);

    const int smem_bytes = (4 * TOK * LDH + 4 * MATH) * 2; // 110592
    cudaFuncSetAttribute(tblock_kernel, cudaFuncAttributeMaxDynamicSharedMemorySize, smem_bytes);

    dim3 grid(Bn / 8);
    dim3 block(NTH);
    tblock_kernel<<<grid, block, smem_bytes>>>(x, bq, bk, bv, bp, b1, b2,
                                               g1, be1, g2, be2, out);
}

// round 9
// speedup vs baseline: 1.1048x; 1.1048x over previous
#include <cuda_runtime.h>
#include <cuda_fp16.h>
#include <math.h>
#include <stdint.h>

#define Bn   16384
#define TOK  128          // tokens per CTA (8 batches x 16)
#define LDH  72           // half stride (144B rows -> conflict-free ldmatrix/stmatrix)
#define LDF  68           // float stride for x2 smem buffer
#define NTH  256
#define EPSV 1e-5f
#define SCL  0.25f

// Weights pre-packed in b-fragment order: per 64x64 matrix, 512 uint4:
//   index = (ks*4 + nbp)*32 + lane ; uint4 = {b0,b1 of n-block 2*nbp ; b0,b1 of 2*nbp+1}
// Matrices: 0-15 head h*{Wq,Wk,Wv,Wp}; 16-19 W1 chunks; 20-23 W2 chunks
__device__ __align__(16) uint4 gWf[24 * 512];

// ---------------- PTX helpers ----------------
__device__ __forceinline__ uint32_t cvta_s(const void* p) {
    return (uint32_t)__cvta_generic_to_shared(p);
}
__device__ __forceinline__ void ldsm_x4(uint32_t* r, uint32_t a) {
    asm volatile("ldmatrix.sync.aligned.m8n8.x4.shared.b16 {%0,%1,%2,%3}, [%4];"
                 : "=r"(r[0]), "=r"(r[1]), "=r"(r[2]), "=r"(r[3]) : "r"(a));
}
__device__ __forceinline__ void ldsm_x4_t(uint32_t* r, uint32_t a) {
    asm volatile("ldmatrix.sync.aligned.m8n8.x4.trans.shared.b16 {%0,%1,%2,%3}, [%4];"
                 : "=r"(r[0]), "=r"(r[1]), "=r"(r[2]), "=r"(r[3]) : "r"(a));
}
__device__ __forceinline__ void stsm_x4(uint32_t a, uint32_t r0, uint32_t r1,
                                        uint32_t r2, uint32_t r3) {
    asm volatile("stmatrix.sync.aligned.m8n8.x4.shared.b16 [%0], {%1,%2,%3,%4};"
                 :: "r"(a), "r"(r0), "r"(r1), "r"(r2), "r"(r3) : "memory");
}
__device__ __forceinline__ void mma16816(float* d, const uint32_t* a, const uint32_t* b) {
    asm volatile("mma.sync.aligned.m16n8k16.row.col.f32.f16.f16.f32 "
                 "{%0,%1,%2,%3},{%4,%5,%6,%7},{%8,%9},{%0,%1,%2,%3};"
                 : "+f"(d[0]), "+f"(d[1]), "+f"(d[2]), "+f"(d[3])
                 : "r"(a[0]), "r"(a[1]), "r"(a[2]), "r"(a[3]), "r"(b[0]), "r"(b[1]));
}
__device__ __forceinline__ uint32_t h2u(float a, float b) {
    __half2 h = __floats2half2_rn(a, b);
    return *(uint32_t*)&h;
}

// ---------------- A-fragment cache (rows mr0..mr0+31, from smem) ----------------
__device__ __forceinline__ void load_afrag(const __half* A, int mr0, int offA, uint32_t af[4][8]) {
    uint32_t aB = cvta_s(A);
#pragma unroll
    for (int i = 0; i < 4; ++i) {
        ldsm_x4(&af[i][0], aB + 2u * (uint32_t)(mr0 * LDH + i * 16 + offA));
        ldsm_x4(&af[i][4], aB + 2u * (uint32_t)((mr0 + 16) * LDH + i * 16 + offA));
    }
}

// 32x32 warp tile GEMM, B fragments via LDG.128 from packed gmem (ncsel = nc0/16)
__device__ __forceinline__ void wgemm_qkv(const uint32_t af[4][8], const uint4* __restrict__ wf,
                                          int ncsel, int lane, float acc[2][4][4]) {
#pragma unroll
    for (int ks = 0; ks < 4; ++ks) {
        uint4 q0 = __ldg(wf + (ks * 4 + ncsel) * 32 + lane);
        uint4 q1 = __ldg(wf + (ks * 4 + ncsel + 1) * 32 + lane);
        uint32_t b0[2] = {q0.x, q0.y}, b1[2] = {q0.z, q0.w};
        uint32_t b2[2] = {q1.x, q1.y}, b3[2] = {q1.z, q1.w};
#pragma unroll
        for (int mi = 0; mi < 2; ++mi) {
            const uint32_t* aa = &af[ks][mi * 4];
            mma16816(acc[mi][0], aa, b0);
            mma16816(acc[mi][1], aa, b1);
            mma16816(acc[mi][2], aa, b2);
            mma16816(acc[mi][3], aa, b3);
        }
    }
}

// 16x64 warp tile GEMM (A in registers as a-frags, full-N B via LDG.128)
__device__ __forceinline__ void wgemm16(const uint32_t a[4][4], const uint4* __restrict__ wf,
                                        int lane, float acc[8][4]) {
#pragma unroll
    for (int ks = 0; ks < 4; ++ks) {
#pragma unroll
        for (int p = 0; p < 4; ++p) {
            uint4 q = __ldg(wf + (ks * 4 + p) * 32 + lane);
            uint32_t bA[2] = {q.x, q.y}, bB[2] = {q.z, q.w};
            mma16816(acc[2 * p],     a[ks], bA);
            mma16816(acc[2 * p + 1], a[ks], bB);
        }
    }
}

__device__ __forceinline__ void init_bias(float acc[2][4][4], const float* bias,
                                          int nc0, int lane) {
    int c2 = 2 * (lane & 3);
#pragma unroll
    for (int j = 0; j < 4; ++j) {
        float2 bv = *(const float2*)(bias + nc0 + 8 * j + c2);
#pragma unroll
        for (int mi = 0; mi < 2; ++mi) {
            acc[mi][j][0] = bv.x; acc[mi][j][1] = bv.y;
            acc[mi][j][2] = bv.x; acc[mi][j][3] = bv.y;
        }
    }
}
__device__ __forceinline__ void init16(float acc[8][4], const float* bias, int c2) {
#pragma unroll
    for (int j = 0; j < 8; ++j) {
        float2 bv = __ldg((const float2*)(bias + 8 * j + c2));
        acc[j][0] = bv.x; acc[j][1] = bv.y;
        acc[j][2] = bv.x; acc[j][3] = bv.y;
    }
}

// C-fragment (fp32) -> A-fragment (half2), optional relu
__device__ __forceinline__ void c2a(const float cc[8][4], uint32_t a[4][4], bool relu) {
#pragma unroll
    for (int ks = 0; ks < 4; ++ks) {
#pragma unroll
        for (int t = 0; t < 2; ++t) {
            float v0 = cc[2 * ks + t][0], v1 = cc[2 * ks + t][1];
            float v2 = cc[2 * ks + t][2], v3 = cc[2 * ks + t][3];
            if (relu) {
                v0 = fmaxf(v0, 0.f); v1 = fmaxf(v1, 0.f);
                v2 = fmaxf(v2, 0.f); v3 = fmaxf(v3, 0.f);
            }
            a[ks][2 * t]     = h2u(v0, v1);
            a[ks][2 * t + 1] = h2u(v2, v3);
        }
    }
}

// fragment epilogue -> half smem via stmatrix (32x32 tile at mr0/nc0)
__device__ __forceinline__ void store_half_tile(__half* C, int mr0, int nc0, int lane,
                                                const float acc[2][4][4]) {
    const uint32_t base = cvta_s(C);
    const int rowoff = ((lane >> 3) & 1) * 8 + (lane & 7);
    const int colsel = lane >> 4;
#pragma unroll
    for (int mi = 0; mi < 2; ++mi)
#pragma unroll
        for (int jj = 0; jj < 2; ++jj) {
            const int j0 = 2 * jj, j1 = 2 * jj + 1;
            uint32_t addr = base + 2u * (uint32_t)((mr0 + 16 * mi + rowoff) * LDH
                                                   + nc0 + 8 * (j0 + colsel));
            stsm_x4(addr, h2u(acc[mi][j0][0], acc[mi][j0][1]),
                          h2u(acc[mi][j0][2], acc[mi][j0][3]),
                          h2u(acc[mi][j1][0], acc[mi][j1][1]),
                          h2u(acc[mi][j1][2], acc[mi][j1][3]));
        }
}

// LayerNorm 64-wide rows (2 threads/row), fp32 gmem src -> half smem dst (stride LDH)
__device__ __forceinline__ void layernorm_half(const float* __restrict__ src,
                                               const float* __restrict__ g,
                                               const float* __restrict__ bb,
                                               __half* dst, int tid) {
    int r = tid >> 1, hf = tid & 1;
    const float* sp = src + r * 64 + hf * 32;
    float4 v[8];
#pragma unroll
    for (int i = 0; i < 8; ++i) v[i] = *(const float4*)(sp + i * 4);
    float s = 0.f, ss = 0.f;
#pragma unroll
    for (int i = 0; i < 8; ++i) {
        s  += v[i].x + v[i].y + v[i].z + v[i].w;
        ss += v[i].x * v[i].x + v[i].y * v[i].y + v[i].z * v[i].z + v[i].w * v[i].w;
    }
    s  += __shfl_xor_sync(0xffffffffu, s, 1);
    ss += __shfl_xor_sync(0xffffffffu, ss, 1);
    float mean = s * (1.f / 64.f);
    float inv  = rsqrtf(ss * (1.f / 64.f) - mean * mean + EPSV);
    __half* dp = dst + r * LDH + hf * 32;
#pragma unroll
    for (int i = 0; i < 8; ++i) {
        int d = hf * 32 + i * 4;
        float o0 = (v[i].x - mean) * inv * __ldg(g + d + 0) + __ldg(bb + d + 0);
        float o1 = (v[i].y - mean) * inv * __ldg(g + d + 1) + __ldg(bb + d + 1);
        float o2 = (v[i].z - mean) * inv * __ldg(g + d + 2) + __ldg(bb + d + 2);
        float o3 = (v[i].w - mean) * inv * __ldg(g + d + 3) + __ldg(bb + d + 3);
        *(__half2*)(dp + i * 4)     = __floats2half2_rn(o0, o1);
        *(__half2*)(dp + i * 4 + 2) = __floats2half2_rn(o2, o3);
    }
}

// per-warp causal attention for batch w; returns ctx as A-fragments (registers)
__device__ __forceinline__ void attention_warp(const __half* sQ, const __half* sK,
                                               const __half* sV, int w, int lane,
                                               int offA, int offK, uint32_t ca[4][4]) {
    const int base = w * 16;
    uint32_t qB = cvta_s(sQ), kB = cvta_s(sK), vB = cvta_s(sV);

    float s0[4] = {0.f, 0.f, 0.f, 0.f};
    float s1[4] = {0.f, 0.f, 0.f, 0.f};
#pragma unroll
    for (int k0 = 0; k0 < 64; k0 += 16) {
        uint32_t aq[4], kb[4];
        ldsm_x4(aq, qB + 2u * (uint32_t)(base * LDH + k0 + offA));
        ldsm_x4(kb, kB + 2u * (uint32_t)(base * LDH + k0 + offK));
        mma16816(s0, aq, kb);
        mma16816(s1, aq, kb + 2);
    }
    const int r = lane >> 2, c2 = 2 * (lane & 3);

    float sc[2][4];
#pragma unroll
    for (int t = 0; t < 2; ++t) {
        const float* sv_ = t ? s1 : s0;
#pragma unroll
        for (int q = 0; q < 4; ++q) {
            int row = r + ((q >> 1) * 8);
            int col = 8 * t + c2 + (q & 1);
            sc[t][q] = (col <= row) ? sv_[q] * SCL : -1e30f;
        }
    }
    float m0 = fmaxf(fmaxf(sc[0][0], sc[0][1]), fmaxf(sc[1][0], sc[1][1]));
    float m1 = fmaxf(fmaxf(sc[0][2], sc[0][3]), fmaxf(sc[1][2], sc[1][3]));
    m0 = fmaxf(m0, __shfl_xor_sync(0xffffffffu, m0, 1));
    m0 = fmaxf(m0, __shfl_xor_sync(0xffffffffu, m0, 2));
    m1 = fmaxf(m1, __shfl_xor_sync(0xffffffffu, m1, 1));
    m1 = fmaxf(m1, __shfl_xor_sync(0xffffffffu, m1, 2));
    float p[2][4];
    float sum0 = 0.f, sum1 = 0.f;
#pragma unroll
    for (int t = 0; t < 2; ++t) {
        p[t][0] = __expf(sc[t][0] - m0); p[t][1] = __expf(sc[t][1] - m0);
        p[t][2] = __expf(sc[t][2] - m1); p[t][3] = __expf(sc[t][3] - m1);
        sum0 += p[t][0] + p[t][1];
        sum1 += p[t][2] + p[t][3];
    }
    sum0 += __shfl_xor_sync(0xffffffffu, sum0, 1);
    sum0 += __shfl_xor_sync(0xffffffffu, sum0, 2);
    sum1 += __shfl_xor_sync(0xffffffffu, sum1, 1);
    sum1 += __shfl_xor_sync(0xffffffffu, sum1, 2);
    float i0 = 1.f / sum0, i1 = 1.f / sum1;

    uint32_t aP[4];
    aP[0] = h2u(p[0][0] * i0, p[0][1] * i0);
    aP[1] = h2u(p[0][2] * i1, p[0][3] * i1);
    aP[2] = h2u(p[1][0] * i0, p[1][1] * i0);
    aP[3] = h2u(p[1][2] * i1, p[1][3] * i1);

    // ctx = P @ V : C-frags converted directly to A-frags (no smem)
#pragma unroll
    for (int pblk = 0; pblk < 4; ++pblk) {
        uint32_t vb[4];
        ldsm_x4_t(vb, vB + 2u * (uint32_t)(base * LDH + pblk * 16 + offA));
        float c0f[4] = {0.f, 0.f, 0.f, 0.f};
        float c1f[4] = {0.f, 0.f, 0.f, 0.f};
        mma16816(c0f, aP, vb);
        mma16816(c1f, aP, vb + 2);
        ca[pblk][0] = h2u(c0f[0], c0f[1]);
        ca[pblk][1] = h2u(c0f[2], c0f[3]);
        ca[pblk][2] = h2u(c1f[0], c1f[1]);
        ca[pblk][3] = h2u(c1f[2], c1f[3]);
    }
}

// ---------------- weight pack: fp32 -> fp16 b-fragment order ----------------
__global__ void pack_weights(const float* __restrict__ Wq, const float* __restrict__ Wk,
                             const float* __restrict__ Wv, const float* __restrict__ Wp,
                             const float* __restrict__ W1, const float* __restrict__ W2) {
    int m = blockIdx.x, tid = threadIdx.x;
    const float* src;
    int stride;
    if (m < 16) {
        int h = m >> 2, t = m & 3;
        const float* w = (t == 0) ? Wq : (t == 1) ? Wk : (t == 2) ? Wv : Wp;
        src = w + h * 4096; stride = 64;
    } else if (m < 20) {
        src = W1 + (m - 16) * 64; stride = 256;   // W1[:, cc*64 .. +63]
    } else {
        src = W2 + (m - 20) * 4096; stride = 64;  // W2[cc*64 .. +63, :]
    }
    for (int idx = tid; idx < 512; idx += 256) {
        int lane = idx & 31, nbp = (idx >> 5) & 3, ks = idx >> 7;
        int c = lane & 3, r = lane >> 2;
        int kb = ks * 16 + 2 * c;
        int n0 = nbp * 16 + r, n1 = n0 + 8;
        uint4 q;
        q.x = h2u(src[kb * stride + n0],       src[(kb + 1) * stride + n0]);
        q.y = h2u(src[(kb + 8) * stride + n0], src[(kb + 9) * stride + n0]);
        q.z = h2u(src[kb * stride + n1],       src[(kb + 1) * stride + n1]);
        q.w = h2u(src[(kb + 8) * stride + n1], src[(kb + 9) * stride + n1]);
        gWf[m * 512 + idx] = q;
    }
}

// ---------------- main fused kernel ----------------
__global__ void __launch_bounds__(NTH, 2)
tblock_kernel(const float* __restrict__ x,
              const float* __restrict__ bq, const float* __restrict__ bk,
              const float* __restrict__ bv, const float* __restrict__ bp,
              const float* __restrict__ b1, const float* __restrict__ b2,
              const float* __restrict__ g1, const float* __restrict__ be1,
              const float* __restrict__ g2, const float* __restrict__ be2,
              float* __restrict__ out) {
    extern __shared__ __align__(16) char smraw[];
    __half* sH = (__half*)smraw;           // 128 x LDH (LN1 out)
    __half* sQ = sH + TOK * LDH;
    __half* sK = sQ + TOK * LDH;
    __half* sV = sK + TOK * LDH;
    float*  x2 = (float*)sQ;               // fp32 x2 buffer over sQ+sK (post-attention)

    const int tid  = threadIdx.x;
    const int lane = tid & 31;
    const int w    = tid >> 5;
    const int g0   = blockIdx.x * TOK;

    const int mr0 = (w >> 1) * 32, nc0 = (w & 1) * 32;
    const int ncsel = (w & 1) * 2;
    const int offA = (lane & 15) * LDH + (lane >> 4) * 8;
    const int offK = ((lane >> 4) * 8 + (lane & 7)) * LDH + ((lane >> 3) & 1) * 8;
    const int r = lane >> 2, c2 = 2 * (lane & 3);

    // LN1: x -> sH (half)
    layernorm_half(x + (size_t)g0 * 64, g1, be1, sH, tid);
    __syncthreads();

    // cache A fragments of sH (reused for all 12 QKV GEMMs)
    uint32_t ah[4][8];
    load_afrag(sH, mr0, offA, ah);

    float pacc[8][4];                      // attn-out accumulator (16x64 tile, batch w)
    init16(pacc, bp, c2);

#pragma unroll 1
    for (int h = 0; h < 4; ++h) {
        const uint4* wh = gWf + h * 4 * 512;
        {
            float acc[2][4][4];
            init_bias(acc, bq + h * 64, nc0, lane);
            wgemm_qkv(ah, wh, ncsel, lane, acc);
            store_half_tile(sQ, mr0, nc0, lane, acc);
        }
        {
            float acc[2][4][4];
            init_bias(acc, bk + h * 64, nc0, lane);
            wgemm_qkv(ah, wh + 512, ncsel, lane, acc);
            store_half_tile(sK, mr0, nc0, lane, acc);
        }
        {
            float acc[2][4][4];
            init_bias(acc, bv + h * 64, nc0, lane);
            wgemm_qkv(ah, wh + 1024, ncsel, lane, acc);
            store_half_tile(sV, mr0, nc0, lane, acc);
        }
        __syncthreads();                   // publish Q/K/V

        uint32_t ca[4][4];
        attention_warp(sQ, sK, sV, w, lane, offA, offK, ca);

        // pacc += ctx_h @ Wp_h  (register-resident, no barrier needed)
        wgemm16(ca, wh + 3 * 512, lane, pacc);

        if (h < 3) __syncthreads();        // all attention reads done before next overwrite
    }
    __syncthreads();                       // protect sQ/sK before x2 aliases them

    // x2 = x + attn_out (+bp already in pacc); keep in regs + stash to smem
    const int row0 = w * 16 + r;
    float x2v[8][4];
#pragma unroll
    for (int j = 0; j < 8; ++j) {
        int col = c2 + 8 * j;
        float2 xa = __ldg((const float2*)(x + (size_t)(g0 + row0) * 64 + col));
        float2 xb = __ldg((const float2*)(x + (size_t)(g0 + row0 + 8) * 64 + col));
        x2v[j][0] = xa.x + pacc[j][0]; x2v[j][1] = xa.y + pacc[j][1];
        x2v[j][2] = xb.x + pacc[j][2]; x2v[j][3] = xb.y + pacc[j][3];
        *(float2*)(x2 + row0 * LDF + col)       = make_float2(x2v[j][0], x2v[j][1]);
        *(float2*)(x2 + (row0 + 8) * LDF + col) = make_float2(x2v[j][2], x2v[j][3]);
    }

    // LN2 fully in registers (rows live within a 4-lane quad)
    float s0 = 0.f, q0 = 0.f, s1 = 0.f, q1 = 0.f;
#pragma unroll
    for (int j = 0; j < 8; ++j) {
        s0 += x2v[j][0] + x2v[j][1];
        q0 += x2v[j][0] * x2v[j][0] + x2v[j][1] * x2v[j][1];
        s1 += x2v[j][2] + x2v[j][3];
        q1 += x2v[j][2] * x2v[j][2] + x2v[j][3] * x2v[j][3];
    }
    s0 += __shfl_xor_sync(0xffffffffu, s0, 1); s0 += __shfl_xor_sync(0xffffffffu, s0, 2);
    q0 += __shfl_xor_sync(0xffffffffu, q0, 1); q0 += __shfl_xor_sync(0xffffffffu, q0, 2);
    s1 += __shfl_xor_sync(0xffffffffu, s1, 1); s1 += __shfl_xor_sync(0xffffffffu, s1, 2);
    q1 += __shfl_xor_sync(0xffffffffu, q1, 1); q1 += __shfl_xor_sync(0xffffffffu, q1, 2);
    float mean0 = s0 * (1.f / 64.f), inv0 = rsqrtf(q0 * (1.f / 64.f) - mean0 * mean0 + EPSV);
    float mean1 = s1 * (1.f / 64.f), inv1 = rsqrtf(q1 * (1.f / 64.f) - mean1 * mean1 + EPSV);

    float nv[8][4];
#pragma unroll
    for (int j = 0; j < 8; ++j) {
        int col = c2 + 8 * j;
        float2 gg = __ldg((const float2*)(g2 + col));
        float2 bb = __ldg((const float2*)(be2 + col));
        nv[j][0] = (x2v[j][0] - mean0) * inv0 * gg.x + bb.x;
        nv[j][1] = (x2v[j][1] - mean0) * inv0 * gg.y + bb.y;
        nv[j][2] = (x2v[j][2] - mean1) * inv1 * gg.x + bb.x;
        nv[j][3] = (x2v[j][3] - mean1) * inv1 * gg.y + bb.y;
    }
    uint32_t A2[4][4];
    c2a(nv, A2, false);

    // FFN: fully register-resident, weights via LDG fragments, zero barriers
    float oacc[8][4];
    init16(oacc, b2, c2);
#pragma unroll 1
    for (int cc = 0; cc < 4; ++cc) {
        float hacc[8][4];
        init16(hacc, b1 + cc * 64, c2);
        wgemm16(A2, gWf + (16 + cc) * 512, lane, hacc);
        uint32_t ha[4][4];
        c2a(hacc, ha, true);               // relu
        wgemm16(ha, gWf + (20 + cc) * 512, lane, oacc);
    }

    // out = x2 + ffn (x2 reloaded from smem; same thread wrote it — no sync)
#pragma unroll
    for (int j = 0; j < 8; ++j) {
        int col = c2 + 8 * j;
        float2 xa = *(const float2*)(x2 + row0 * LDF + col);
        float2 xb = *(const float2*)(x2 + (row0 + 8) * LDF + col);
        *(float2*)(out + (size_t)(g0 + row0) * 64 + col) =
            make_float2(xa.x + oacc[j][0], xa.y + oacc[j][1]);
        *(float2*)(out + (size_t)(g0 + row0 + 8) * 64 + col) =
            make_float2(xb.x + oacc[j][2], xb.y + oacc[j][3]);
    }
}

extern "C" void kernel_launch(void* const* d_in, const int* in_sizes, int n_in,
                              void* d_out, int out_size) {
    const float* x   = (const float*)d_in[0];
    const float* Wq  = (const float*)d_in[1];
    const float* bq  = (const float*)d_in[2];
    const float* Wk  = (const float*)d_in[3];
    const float* bk  = (const float*)d_in[4];
    const float* Wv  = (const float*)d_in[5];
    const float* bv  = (const float*)d_in[6];
    const float* Wp  = (const float*)d_in[7];
    const float* bp  = (const float*)d_in[8];
    const float* W1  = (const float*)d_in[9];
    const float* b1  = (const float*)d_in[10];
    const float* W2  = (const float*)d_in[11];
    const float* b2  = (const float*)d_in[12];
    const float* g1  = (const float*)d_in[13];
    const float* be1 = (const float*)d_in[14];
    const float* g2  = (const float*)d_in[15];
    const float* be2 = (const float*)d_in[16];
    float* out = (float*)d_out;

    pack_weights<<<24, 256>>>(Wq, Wk, Wv, Wp, W1, W2);

    const int smem_bytes = 4 * TOK * LDH * 2;   // 73728
    cudaFuncSetAttribute(tblock_kernel, cudaFuncAttributeMaxDynamicSharedMemorySize, smem_bytes);

    dim3 grid(Bn / 8);
    dim3 block(NTH);
    tblock_kernel<<<grid, block, smem_bytes>>>(x, bq, bk, bv, bp, b1, b2,
                                               g1, be1, g2, be2, out);
}

// round 10
// speedup vs baseline: 1.1384x; 1.0304x over previous
#include <cuda_runtime.h>
#include <cuda_fp16.h>
#include <math.h>
#include <stdint.h>

#define Bn   16384
#define TOK  128          // tokens per CTA (8 batches x 16)
#define LDF  68           // float stride for x/x2 smem stash
#define NTH  256
#define EPSV 1e-5f
#define SCL  0.25f

// Weights pre-packed in b-fragment order: per 64x64 matrix, 512 uint4:
//   index = (ks*4 + nbp)*32 + lane ; uint4 = {b0,b1 of n-block 2*nbp ; b0,b1 of 2*nbp+1}
// Matrices: 0-15 head h*{Wq,Wk,Wv,Wp}; 16-19 W1 chunks; 20-23 W2 chunks
__device__ __align__(16) uint4 gWf[24 * 512];

// ---------------- PTX helpers ----------------
__device__ __forceinline__ void mma16816(float* d, const uint32_t* a, const uint32_t* b) {
    asm volatile("mma.sync.aligned.m16n8k16.row.col.f32.f16.f16.f32 "
                 "{%0,%1,%2,%3},{%4,%5,%6,%7},{%8,%9},{%0,%1,%2,%3};"
                 : "+f"(d[0]), "+f"(d[1]), "+f"(d[2]), "+f"(d[3])
                 : "r"(a[0]), "r"(a[1]), "r"(a[2]), "r"(a[3]), "r"(b[0]), "r"(b[1]));
}
__device__ __forceinline__ uint32_t h2u(float a, float b) {
    __half2 h = __floats2half2_rn(a, b);
    return *(uint32_t*)&h;
}
__device__ __forceinline__ uint32_t movm(uint32_t s) {
    uint32_t d;
    asm volatile("movmatrix.sync.aligned.m8n8.trans.b16 %0, %1;" : "=r"(d) : "r"(s));
    return d;
}

// 16x64 warp-tile GEMM: A in a-frags (k=64 -> 4 k-steps), B via LDG.128 fragments
__device__ __forceinline__ void wgemm16(const uint32_t a[4][4], const uint4* __restrict__ wf,
                                        int lane, float acc[8][4]) {
#pragma unroll
    for (int ks = 0; ks < 4; ++ks) {
#pragma unroll
        for (int p = 0; p < 4; ++p) {
            uint4 q = __ldg(wf + (ks * 4 + p) * 32 + lane);
            uint32_t bA[2] = {q.x, q.y}, bB[2] = {q.z, q.w};
            mma16816(acc[2 * p],     a[ks], bA);
            mma16816(acc[2 * p + 1], a[ks], bB);
        }
    }
}
__device__ __forceinline__ void init16(float acc[8][4], const float* bias, int c2) {
#pragma unroll
    for (int j = 0; j < 8; ++j) {
        float2 bv = __ldg((const float2*)(bias + 8 * j + c2));
        acc[j][0] = bv.x; acc[j][1] = bv.y;
        acc[j][2] = bv.x; acc[j][3] = bv.y;
    }
}
// C-fragment (fp32, 16x64) -> A-fragment (half2), optional relu
__device__ __forceinline__ void c2a(const float cc[8][4], uint32_t a[4][4], bool relu) {
#pragma unroll
    for (int ks = 0; ks < 4; ++ks) {
#pragma unroll
        for (int t = 0; t < 2; ++t) {
            float v0 = cc[2 * ks + t][0], v1 = cc[2 * ks + t][1];
            float v2 = cc[2 * ks + t][2], v3 = cc[2 * ks + t][3];
            if (relu) {
                v0 = fmaxf(v0, 0.f); v1 = fmaxf(v1, 0.f);
                v2 = fmaxf(v2, 0.f); v3 = fmaxf(v3, 0.f);
            }
            a[ks][2 * t]     = h2u(v0, v1);
            a[ks][2 * t + 1] = h2u(v2, v3);
        }
    }
}

// ---------------- weight pack: fp32 -> fp16 b-fragment order ----------------
__global__ void pack_weights(const float* __restrict__ Wq, const float* __restrict__ Wk,
                             const float* __restrict__ Wv, const float* __restrict__ Wp,
                             const float* __restrict__ W1, const float* __restrict__ W2) {
    int m = blockIdx.x, tid = threadIdx.x;
    const float* src;
    int stride;
    if (m < 16) {
        int h = m >> 2, t = m & 3;
        const float* w = (t == 0) ? Wq : (t == 1) ? Wk : (t == 2) ? Wv : Wp;
        src = w + h * 4096; stride = 64;
    } else if (m < 20) {
        src = W1 + (m - 16) * 64; stride = 256;   // W1[:, cc*64 .. +63]
    } else {
        src = W2 + (m - 20) * 4096; stride = 64;  // W2[cc*64 .. +63, :]
    }
    for (int idx = tid; idx < 512; idx += 256) {
        int lane = idx & 31, nbp = (idx >> 5) & 3, ks = idx >> 7;
        int c = lane & 3, r = lane >> 2;
        int kb = ks * 16 + 2 * c;
        int n0 = nbp * 16 + r, n1 = n0 + 8;
        uint4 q;
        q.x = h2u(src[kb * stride + n0],       src[(kb + 1) * stride + n0]);
        q.y = h2u(src[(kb + 8) * stride + n0], src[(kb + 9) * stride + n0]);
        q.z = h2u(src[kb * stride + n1],       src[(kb + 1) * stride + n1]);
        q.w = h2u(src[(kb + 8) * stride + n1], src[(kb + 9) * stride + n1]);
        gWf[m * 512 + idx] = q;
    }
}

// ---------------- main fused kernel: fully warp-local, zero barriers ----------------
__global__ void __launch_bounds__(NTH, 2)
tblock_kernel(const float* __restrict__ x,
              const float* __restrict__ bq, const float* __restrict__ bk,
              const float* __restrict__ bv, const float* __restrict__ bp,
              const float* __restrict__ b1, const float* __restrict__ b2,
              const float* __restrict__ g1, const float* __restrict__ be1,
              const float* __restrict__ g2, const float* __restrict__ be2,
              float* __restrict__ out) {
    __shared__ float xs[TOK * LDF];        // raw x, later x2 (same-thread use only)

    const int tid  = threadIdx.x;
    const int lane = tid & 31;
    const int w    = tid >> 5;
    const int g0   = blockIdx.x * TOK;
    const int r    = lane >> 2, c2 = 2 * (lane & 3);
    const int row0 = w * 16 + r;           // this lane's rows: row0, row0+8

    // ---- load x in fragment layout + stash raw to smem ----
    float xv[8][4];
#pragma unroll
    for (int j = 0; j < 8; ++j) {
        int col = c2 + 8 * j;
        float2 xa = __ldg((const float2*)(x + (size_t)(g0 + row0) * 64 + col));
        float2 xb = __ldg((const float2*)(x + (size_t)(g0 + row0 + 8) * 64 + col));
        xv[j][0] = xa.x; xv[j][1] = xa.y; xv[j][2] = xb.x; xv[j][3] = xb.y;
        *(float2*)(xs + row0 * LDF + col)       = xa;
        *(float2*)(xs + (row0 + 8) * LDF + col) = xb;
    }

    // ---- LN1 in registers (quad shuffles) ----
    {
        float s0 = 0.f, q0 = 0.f, s1 = 0.f, q1 = 0.f;
#pragma unroll
        for (int j = 0; j < 8; ++j) {
            s0 += xv[j][0] + xv[j][1];
            q0 += xv[j][0] * xv[j][0] + xv[j][1] * xv[j][1];
            s1 += xv[j][2] + xv[j][3];
            q1 += xv[j][2] * xv[j][2] + xv[j][3] * xv[j][3];
        }
        s0 += __shfl_xor_sync(0xffffffffu, s0, 1); s0 += __shfl_xor_sync(0xffffffffu, s0, 2);
        q0 += __shfl_xor_sync(0xffffffffu, q0, 1); q0 += __shfl_xor_sync(0xffffffffu, q0, 2);
        s1 += __shfl_xor_sync(0xffffffffu, s1, 1); s1 += __shfl_xor_sync(0xffffffffu, s1, 2);
        q1 += __shfl_xor_sync(0xffffffffu, q1, 1); q1 += __shfl_xor_sync(0xffffffffu, q1, 2);
        float mean0 = s0 * (1.f / 64.f), inv0 = rsqrtf(q0 * (1.f / 64.f) - mean0 * mean0 + EPSV);
        float mean1 = s1 * (1.f / 64.f), inv1 = rsqrtf(q1 * (1.f / 64.f) - mean1 * mean1 + EPSV);
#pragma unroll
        for (int j = 0; j < 8; ++j) {
            int col = c2 + 8 * j;
            float2 gg = __ldg((const float2*)(g1 + col));
            float2 bb = __ldg((const float2*)(be1 + col));
            xv[j][0] = (xv[j][0] - mean0) * inv0 * gg.x + bb.x;
            xv[j][1] = (xv[j][1] - mean0) * inv0 * gg.y + bb.y;
            xv[j][2] = (xv[j][2] - mean1) * inv1 * gg.x + bb.x;
            xv[j][3] = (xv[j][3] - mean1) * inv1 * gg.y + bb.y;
        }
    }
    uint32_t ah16[4][4];
    c2a(xv, ah16, false);                  // xv dead (raw x stashed in xs)

    float pacc[8][4];                      // attention output accumulator (16x64)
    init16(pacc, bp, c2);

    // ---- per-head attention, fully register-resident ----
#pragma unroll 1
    for (int h = 0; h < 4; ++h) {
        const uint4* wh = gWf + h * 2048;

        // Q
        uint32_t qa[4][4];
        {
            float qacc[8][4];
            init16(qacc, bq + h * 64, c2);
            wgemm16(ah16, wh, lane, qacc);
            c2a(qacc, qa, false);
        }
        // K -> B-fragments (pure repack: C-frag layout == B-frag layout here)
        uint32_t kb[4][4];
        {
            float kacc[8][4];
            init16(kacc, bk + h * 64, c2);
            wgemm16(ah16, wh + 512, lane, kacc);
#pragma unroll
            for (int ks = 0; ks < 4; ++ks) {
                kb[ks][0] = h2u(kacc[2 * ks][0],     kacc[2 * ks][1]);
                kb[ks][1] = h2u(kacc[2 * ks + 1][0], kacc[2 * ks + 1][1]);
                kb[ks][2] = h2u(kacc[2 * ks][2],     kacc[2 * ks][3]);
                kb[ks][3] = h2u(kacc[2 * ks + 1][2], kacc[2 * ks + 1][3]);
            }
        }
        // S = Q @ K^T  (16x16: keys 0-7 in sS0, keys 8-15 in sS1)
        float sS0[4] = {0.f, 0.f, 0.f, 0.f};
        float sS1[4] = {0.f, 0.f, 0.f, 0.f};
#pragma unroll
        for (int ks = 0; ks < 4; ++ks) {
            mma16816(sS0, qa[ks], &kb[ks][0]);
            mma16816(sS1, qa[ks], &kb[ks][2]);
        }
        // causal softmax (rows r, r+8; cols c2(+1) + 8-block)
        uint32_t aP[4];
        {
            float sc[2][4];
#pragma unroll
            for (int t = 0; t < 2; ++t) {
                const float* sv_ = t ? sS1 : sS0;
#pragma unroll
                for (int q = 0; q < 4; ++q) {
                    int row = r + ((q >> 1) * 8);
                    int col = 8 * t + c2 + (q & 1);
                    sc[t][q] = (col <= row) ? sv_[q] * SCL : -1e30f;
                }
            }
            float m0 = fmaxf(fmaxf(sc[0][0], sc[0][1]), fmaxf(sc[1][0], sc[1][1]));
            float m1 = fmaxf(fmaxf(sc[0][2], sc[0][3]), fmaxf(sc[1][2], sc[1][3]));
            m0 = fmaxf(m0, __shfl_xor_sync(0xffffffffu, m0, 1));
            m0 = fmaxf(m0, __shfl_xor_sync(0xffffffffu, m0, 2));
            m1 = fmaxf(m1, __shfl_xor_sync(0xffffffffu, m1, 1));
            m1 = fmaxf(m1, __shfl_xor_sync(0xffffffffu, m1, 2));
            float p[2][4];
            float sum0 = 0.f, sum1 = 0.f;
#pragma unroll
            for (int t = 0; t < 2; ++t) {
                p[t][0] = __expf(sc[t][0] - m0); p[t][1] = __expf(sc[t][1] - m0);
                p[t][2] = __expf(sc[t][2] - m1); p[t][3] = __expf(sc[t][3] - m1);
                sum0 += p[t][0] + p[t][1];
                sum1 += p[t][2] + p[t][3];
            }
            sum0 += __shfl_xor_sync(0xffffffffu, sum0, 1);
            sum0 += __shfl_xor_sync(0xffffffffu, sum0, 2);
            sum1 += __shfl_xor_sync(0xffffffffu, sum1, 1);
            sum1 += __shfl_xor_sync(0xffffffffu, sum1, 2);
            float i0 = 1.f / sum0, i1 = 1.f / sum1;
            aP[0] = h2u(p[0][0] * i0, p[0][1] * i0);
            aP[1] = h2u(p[0][2] * i1, p[0][3] * i1);
            aP[2] = h2u(p[1][0] * i0, p[1][1] * i0);
            aP[3] = h2u(p[1][2] * i1, p[1][3] * i1);
        }
        // V -> B-fragments via movmatrix (8x8 transposes), ctx = P @ V
        float cacc[8][4];
        {
            float vacc[8][4];
            init16(vacc, bv + h * 64, c2);
            wgemm16(ah16, wh + 1024, lane, vacc);
#pragma unroll
            for (int f = 0; f < 8; ++f) {
                uint32_t bb[2];
                bb[0] = movm(h2u(vacc[f][0], vacc[f][1]));   // keys 0-7
                bb[1] = movm(h2u(vacc[f][2], vacc[f][3]));   // keys 8-15
                cacc[f][0] = 0.f; cacc[f][1] = 0.f; cacc[f][2] = 0.f; cacc[f][3] = 0.f;
                mma16816(cacc[f], aP, bb);
            }
        }
        // pacc += ctx @ Wp_h
        uint32_t ca[4][4];
        c2a(cacc, ca, false);
        wgemm16(ca, wh + 1536, lane, pacc);
    }

    // ---- x2 = x + attn_out; stash to smem; LN2 in registers ----
    float x2v[8][4];
#pragma unroll
    for (int j = 0; j < 8; ++j) {
        int col = c2 + 8 * j;
        float2 xa = *(const float2*)(xs + row0 * LDF + col);
        float2 xb = *(const float2*)(xs + (row0 + 8) * LDF + col);
        x2v[j][0] = xa.x + pacc[j][0]; x2v[j][1] = xa.y + pacc[j][1];
        x2v[j][2] = xb.x + pacc[j][2]; x2v[j][3] = xb.y + pacc[j][3];
        *(float2*)(xs + row0 * LDF + col)       = make_float2(x2v[j][0], x2v[j][1]);
        *(float2*)(xs + (row0 + 8) * LDF + col) = make_float2(x2v[j][2], x2v[j][3]);
    }
    uint32_t A2[4][4];
    {
        float s0 = 0.f, q0 = 0.f, s1 = 0.f, q1 = 0.f;
#pragma unroll
        for (int j = 0; j < 8; ++j) {
            s0 += x2v[j][0] + x2v[j][1];
            q0 += x2v[j][0] * x2v[j][0] + x2v[j][1] * x2v[j][1];
            s1 += x2v[j][2] + x2v[j][3];
            q1 += x2v[j][2] * x2v[j][2] + x2v[j][3] * x2v[j][3];
        }
        s0 += __shfl_xor_sync(0xffffffffu, s0, 1); s0 += __shfl_xor_sync(0xffffffffu, s0, 2);
        q0 += __shfl_xor_sync(0xffffffffu, q0, 1); q0 += __shfl_xor_sync(0xffffffffu, q0, 2);
        s1 += __shfl_xor_sync(0xffffffffu, s1, 1); s1 += __shfl_xor_sync(0xffffffffu, s1, 2);
        q1 += __shfl_xor_sync(0xffffffffu, q1, 1); q1 += __shfl_xor_sync(0xffffffffu, q1, 2);
        float mean0 = s0 * (1.f / 64.f), inv0 = rsqrtf(q0 * (1.f / 64.f) - mean0 * mean0 + EPSV);
        float mean1 = s1 * (1.f / 64.f), inv1 = rsqrtf(q1 * (1.f / 64.f) - mean1 * mean1 + EPSV);
        float nv[8][4];
#pragma unroll
        for (int j = 0; j < 8; ++j) {
            int col = c2 + 8 * j;
            float2 gg = __ldg((const float2*)(g2 + col));
            float2 bb = __ldg((const float2*)(be2 + col));
            nv[j][0] = (x2v[j][0] - mean0) * inv0 * gg.x + bb.x;
            nv[j][1] = (x2v[j][1] - mean0) * inv0 * gg.y + bb.y;
            nv[j][2] = (x2v[j][2] - mean1) * inv1 * gg.x + bb.x;
            nv[j][3] = (x2v[j][3] - mean1) * inv1 * gg.y + bb.y;
        }
        c2a(nv, A2, false);
    }

    // ---- FFN: register-resident, zero barriers ----
    float oacc[8][4];
    init16(oacc, b2, c2);
#pragma unroll 1
    for (int cc = 0; cc < 4; ++cc) {
        float hacc[8][4];
        init16(hacc, b1 + cc * 64, c2);
        wgemm16(A2, gWf + (16 + cc) * 512, lane, hacc);
        uint32_t ha[4][4];
        c2a(hacc, ha, true);               // relu
        wgemm16(ha, gWf + (20 + cc) * 512, lane, oacc);
    }

    // ---- out = x2 + ffn ----
#pragma unroll
    for (int j = 0; j < 8; ++j) {
        int col = c2 + 8 * j;
        float2 xa = *(const float2*)(xs + row0 * LDF + col);
        float2 xb = *(const float2*)(xs + (row0 + 8) * LDF + col);
        *(float2*)(out + (size_t)(g0 + row0) * 64 + col) =
            make_float2(xa.x + oacc[j][0], xa.y + oacc[j][1]);
        *(float2*)(out + (size_t)(g0 + row0 + 8) * 64 + col) =
            make_float2(xb.x + oacc[j][2], xb.y + oacc[j][3]);
    }
}

extern "C" void kernel_launch(void* const* d_in, const int* in_sizes, int n_in,
                              void* d_out, int out_size) {
    const float* x   = (const float*)d_in[0];
    const float* Wq  = (const float*)d_in[1];
    const float* bq  = (const float*)d_in[2];
    const float* Wk  = (const float*)d_in[3];
    const float* bk  = (const float*)d_in[4];
    const float* Wv  = (const float*)d_in[5];
    const float* bv  = (const float*)d_in[6];
    const float* Wp  = (const float*)d_in[7];
    const float* bp  = (const float*)d_in[8];
    const float* W1  = (const float*)d_in[9];
    const float* b1  = (const float*)d_in[10];
    const float* W2  = (const float*)d_in[11];
    const float* b2  = (const float*)d_in[12];
    const float* g1  = (const float*)d_in[13];
    const float* be1 = (const float*)d_in[14];
    const float* g2  = (const float*)d_in[15];
    const float* be2 = (const float*)d_in[16];
    float* out = (float*)d_out;

    pack_weights<<<24, 256>>>(Wq, Wk, Wv, Wp, W1, W2);

    dim3 grid(Bn / 8);
    dim3 block(NTH);
    tblock_kernel<<<grid, block>>>(x, bq, bk, bv, bp, b1, b2,
                                   g1, be1, g2, be2, out);
}

// round 11
// speedup vs baseline: 1.2550x; 1.1025x over previous
#include <cuda_runtime.h>
#include <cuda_fp16.h>
#include <math.h>
#include <stdint.h>

#define Bn   16384
#define TOK  256          // tokens per CTA (16 batches; 2 per warp)
#define LDF  68           // float stride for x/x2 smem stash
#define NTH  256
#define EPSV 1e-5f
#define SCL  0.25f

// Weights pre-packed in b-fragment order: per 64x64 matrix, 512 uint4:
//   index = (ks*4 + nbp)*32 + lane ; uint4 = {b0,b1 of n-block 2*nbp ; b0,b1 of 2*nbp+1}
// Matrices: 0-15 head h*{Wq,Wk,Wv,Wp}; 16-19 W1 chunks; 20-23 W2 chunks
__device__ __align__(16) uint4 gWf[24 * 512];

// ---------------- PTX helpers ----------------
__device__ __forceinline__ void mma16816(float* d, const uint32_t* a, const uint32_t* b) {
    asm volatile("mma.sync.aligned.m16n8k16.row.col.f32.f16.f16.f32 "
                 "{%0,%1,%2,%3},{%4,%5,%6,%7},{%8,%9},{%0,%1,%2,%3};"
                 : "+f"(d[0]), "+f"(d[1]), "+f"(d[2]), "+f"(d[3])
                 : "r"(a[0]), "r"(a[1]), "r"(a[2]), "r"(a[3]), "r"(b[0]), "r"(b[1]));
}
__device__ __forceinline__ uint32_t h2u(float a, float b) {
    __half2 h = __floats2half2_rn(a, b);
    return *(uint32_t*)&h;
}
__device__ __forceinline__ uint32_t movm(uint32_t s) {
    uint32_t d;
    asm volatile("movmatrix.sync.aligned.m8n8.trans.b16 %0, %1;" : "=r"(d) : "r"(s));
    return d;
}

// 32x64 (2 batches) warp-tile GEMM: each B fragment loaded ONCE, used for both batches
__device__ __forceinline__ void wgemm16x2(const uint32_t a[2][4][4],
                                          const uint4* __restrict__ wf,
                                          int lane, float acc[2][8][4]) {
#pragma unroll
    for (int ks = 0; ks < 4; ++ks) {
#pragma unroll
        for (int p = 0; p < 4; ++p) {
            uint4 q = __ldg(wf + (ks * 4 + p) * 32 + lane);
            uint32_t bA[2] = {q.x, q.y}, bB[2] = {q.z, q.w};
#pragma unroll
            for (int bi = 0; bi < 2; ++bi) {
                mma16816(acc[bi][2 * p],     a[bi][ks], bA);
                mma16816(acc[bi][2 * p + 1], a[bi][ks], bB);
            }
        }
    }
}
__device__ __forceinline__ void init16(float acc[8][4], const float* bias, int c2) {
#pragma unroll
    for (int j = 0; j < 8; ++j) {
        float2 bv = __ldg((const float2*)(bias + 8 * j + c2));
        acc[j][0] = bv.x; acc[j][1] = bv.y;
        acc[j][2] = bv.x; acc[j][3] = bv.y;
    }
}
// C-fragment (fp32, 16x64) -> A-fragment (half2), optional relu
__device__ __forceinline__ void c2a(const float cc[8][4], uint32_t a[4][4], bool relu) {
#pragma unroll
    for (int ks = 0; ks < 4; ++ks) {
#pragma unroll
        for (int t = 0; t < 2; ++t) {
            float v0 = cc[2 * ks + t][0], v1 = cc[2 * ks + t][1];
            float v2 = cc[2 * ks + t][2], v3 = cc[2 * ks + t][3];
            if (relu) {
                v0 = fmaxf(v0, 0.f); v1 = fmaxf(v1, 0.f);
                v2 = fmaxf(v2, 0.f); v3 = fmaxf(v3, 0.f);
            }
            a[ks][2 * t]     = h2u(v0, v1);
            a[ks][2 * t + 1] = h2u(v2, v3);
        }
    }
}

// ---------------- weight pack: fp32 -> fp16 b-fragment order ----------------
__global__ void pack_weights(const float* __restrict__ Wq, const float* __restrict__ Wk,
                             const float* __restrict__ Wv, const float* __restrict__ Wp,
                             const float* __restrict__ W1, const float* __restrict__ W2) {
    int m = blockIdx.x, tid = threadIdx.x;
    const float* src;
    int stride;
    if (m < 16) {
        int h = m >> 2, t = m & 3;
        const float* w = (t == 0) ? Wq : (t == 1) ? Wk : (t == 2) ? Wv : Wp;
        src = w + h * 4096; stride = 64;
    } else if (m < 20) {
        src = W1 + (m - 16) * 64; stride = 256;   // W1[:, cc*64 .. +63]
    } else {
        src = W2 + (m - 20) * 4096; stride = 64;  // W2[cc*64 .. +63, :]
    }
    for (int idx = tid; idx < 512; idx += 256) {
        int lane = idx & 31, nbp = (idx >> 5) & 3, ks = idx >> 7;
        int c = lane & 3, r = lane >> 2;
        int kb = ks * 16 + 2 * c;
        int n0 = nbp * 16 + r, n1 = n0 + 8;
        uint4 q;
        q.x = h2u(src[kb * stride + n0],       src[(kb + 1) * stride + n0]);
        q.y = h2u(src[(kb + 8) * stride + n0], src[(kb + 9) * stride + n0]);
        q.z = h2u(src[kb * stride + n1],       src[(kb + 1) * stride + n1]);
        q.w = h2u(src[(kb + 8) * stride + n1], src[(kb + 9) * stride + n1]);
        gWf[m * 512 + idx] = q;
    }
}

// ---------------- main fused kernel: warp-local, 2 batches/warp, zero barriers ------
__global__ void __launch_bounds__(NTH, 1)
tblock_kernel(const float* __restrict__ x,
              const float* __restrict__ bq, const float* __restrict__ bk,
              const float* __restrict__ bv, const float* __restrict__ bp,
              const float* __restrict__ b1, const float* __restrict__ b2,
              const float* __restrict__ g1, const float* __restrict__ be1,
              const float* __restrict__ g2, const float* __restrict__ be2,
              float* __restrict__ out) {
    extern __shared__ __align__(16) float xs[];   // TOK x LDF: raw x, later x2

    const int tid  = threadIdx.x;
    const int lane = tid & 31;
    const int w    = tid >> 5;
    const int g0   = blockIdx.x * TOK;
    const int r    = lane >> 2, c2 = 2 * (lane & 3);
    const int row0[2] = { (2 * w) * 16 + r, (2 * w + 1) * 16 + r };

    // ---- load x in fragment layout + stash raw to smem; LN1 in registers ----
    uint32_t ah16[2][4][4];
#pragma unroll
    for (int bi = 0; bi < 2; ++bi) {
        float xv[8][4];
#pragma unroll
        for (int j = 0; j < 8; ++j) {
            int col = c2 + 8 * j;
            float2 xa = __ldg((const float2*)(x + (size_t)(g0 + row0[bi]) * 64 + col));
            float2 xb = __ldg((const float2*)(x + (size_t)(g0 + row0[bi] + 8) * 64 + col));
            xv[j][0] = xa.x; xv[j][1] = xa.y; xv[j][2] = xb.x; xv[j][3] = xb.y;
            *(float2*)(xs + row0[bi] * LDF + col)       = xa;
            *(float2*)(xs + (row0[bi] + 8) * LDF + col) = xb;
        }
        float s0 = 0.f, q0 = 0.f, s1 = 0.f, q1 = 0.f;
#pragma unroll
        for (int j = 0; j < 8; ++j) {
            s0 += xv[j][0] + xv[j][1];
            q0 += xv[j][0] * xv[j][0] + xv[j][1] * xv[j][1];
            s1 += xv[j][2] + xv[j][3];
            q1 += xv[j][2] * xv[j][2] + xv[j][3] * xv[j][3];
        }
        s0 += __shfl_xor_sync(0xffffffffu, s0, 1); s0 += __shfl_xor_sync(0xffffffffu, s0, 2);
        q0 += __shfl_xor_sync(0xffffffffu, q0, 1); q0 += __shfl_xor_sync(0xffffffffu, q0, 2);
        s1 += __shfl_xor_sync(0xffffffffu, s1, 1); s1 += __shfl_xor_sync(0xffffffffu, s1, 2);
        q1 += __shfl_xor_sync(0xffffffffu, q1, 1); q1 += __shfl_xor_sync(0xffffffffu, q1, 2);
        float mean0 = s0 * (1.f / 64.f), inv0 = rsqrtf(q0 * (1.f / 64.f) - mean0 * mean0 + EPSV);
        float mean1 = s1 * (1.f / 64.f), inv1 = rsqrtf(q1 * (1.f / 64.f) - mean1 * mean1 + EPSV);
#pragma unroll
        for (int j = 0; j < 8; ++j) {
            int col = c2 + 8 * j;
            float2 gg = __ldg((const float2*)(g1 + col));
            float2 bb = __ldg((const float2*)(be1 + col));
            xv[j][0] = (xv[j][0] - mean0) * inv0 * gg.x + bb.x;
            xv[j][1] = (xv[j][1] - mean0) * inv0 * gg.y + bb.y;
            xv[j][2] = (xv[j][2] - mean1) * inv1 * gg.x + bb.x;
            xv[j][3] = (xv[j][3] - mean1) * inv1 * gg.y + bb.y;
        }
        c2a(xv, ah16[bi], false);
    }

    float pacc[2][8][4];                   // attention output accumulators
    init16(pacc[0], bp, c2);
    init16(pacc[1], bp, c2);

    // ---- per-head attention, register-resident, weights loaded once per warp ----
#pragma unroll 1
    for (int h = 0; h < 4; ++h) {
        const uint4* wh = gWf + h * 2048;

        // Q (both batches)
        uint32_t qa[2][4][4];
        {
            float qacc[2][8][4];
            init16(qacc[0], bq + h * 64, c2);
            init16(qacc[1], bq + h * 64, c2);
            wgemm16x2(ah16, wh, lane, qacc);
            c2a(qacc[0], qa[0], false);
            c2a(qacc[1], qa[1], false);
        }
        // K -> B-fragments (pure repack)
        uint32_t kb[2][4][4];
        {
            float kacc[2][8][4];
            init16(kacc[0], bk + h * 64, c2);
            init16(kacc[1], bk + h * 64, c2);
            wgemm16x2(ah16, wh + 512, lane, kacc);
#pragma unroll
            for (int bi = 0; bi < 2; ++bi)
#pragma unroll
                for (int ks = 0; ks < 4; ++ks) {
                    kb[bi][ks][0] = h2u(kacc[bi][2 * ks][0],     kacc[bi][2 * ks][1]);
                    kb[bi][ks][1] = h2u(kacc[bi][2 * ks + 1][0], kacc[bi][2 * ks + 1][1]);
                    kb[bi][ks][2] = h2u(kacc[bi][2 * ks][2],     kacc[bi][2 * ks][3]);
                    kb[bi][ks][3] = h2u(kacc[bi][2 * ks + 1][2], kacc[bi][2 * ks + 1][3]);
                }
        }
        // S = Q K^T, causal softmax -> aP per batch
        uint32_t aP[2][4];
#pragma unroll
        for (int bi = 0; bi < 2; ++bi) {
            float sS0[4] = {0.f, 0.f, 0.f, 0.f};
            float sS1[4] = {0.f, 0.f, 0.f, 0.f};
#pragma unroll
            for (int ks = 0; ks < 4; ++ks) {
                mma16816(sS0, qa[bi][ks], &kb[bi][ks][0]);
                mma16816(sS1, qa[bi][ks], &kb[bi][ks][2]);
            }
            float sc[2][4];
#pragma unroll
            for (int t = 0; t < 2; ++t) {
                const float* sv_ = t ? sS1 : sS0;
#pragma unroll
                for (int q = 0; q < 4; ++q) {
                    int row = r + ((q >> 1) * 8);
                    int col = 8 * t + c2 + (q & 1);
                    sc[t][q] = (col <= row) ? sv_[q] * SCL : -1e30f;
                }
            }
            float m0 = fmaxf(fmaxf(sc[0][0], sc[0][1]), fmaxf(sc[1][0], sc[1][1]));
            float m1 = fmaxf(fmaxf(sc[0][2], sc[0][3]), fmaxf(sc[1][2], sc[1][3]));
            m0 = fmaxf(m0, __shfl_xor_sync(0xffffffffu, m0, 1));
            m0 = fmaxf(m0, __shfl_xor_sync(0xffffffffu, m0, 2));
            m1 = fmaxf(m1, __shfl_xor_sync(0xffffffffu, m1, 1));
            m1 = fmaxf(m1, __shfl_xor_sync(0xffffffffu, m1, 2));
            float p[2][4];
            float sum0 = 0.f, sum1 = 0.f;
#pragma unroll
            for (int t = 0; t < 2; ++t) {
                p[t][0] = __expf(sc[t][0] - m0); p[t][1] = __expf(sc[t][1] - m0);
                p[t][2] = __expf(sc[t][2] - m1); p[t][3] = __expf(sc[t][3] - m1);
                sum0 += p[t][0] + p[t][1];
                sum1 += p[t][2] + p[t][3];
            }
            sum0 += __shfl_xor_sync(0xffffffffu, sum0, 1);
            sum0 += __shfl_xor_sync(0xffffffffu, sum0, 2);
            sum1 += __shfl_xor_sync(0xffffffffu, sum1, 1);
            sum1 += __shfl_xor_sync(0xffffffffu, sum1, 2);
            float i0 = 1.f / sum0, i1 = 1.f / sum1;
            aP[bi][0] = h2u(p[0][0] * i0, p[0][1] * i0);
            aP[bi][1] = h2u(p[0][2] * i1, p[0][3] * i1);
            aP[bi][2] = h2u(p[1][0] * i0, p[1][1] * i0);
            aP[bi][3] = h2u(p[1][2] * i1, p[1][3] * i1);
        }
        // V (both batches), ctx = P @ V via movmatrix, proj accumulate
        {
            float vacc[2][8][4];
            init16(vacc[0], bv + h * 64, c2);
            init16(vacc[1], bv + h * 64, c2);
            wgemm16x2(ah16, wh + 1024, lane, vacc);
            uint32_t ca[2][4][4];
#pragma unroll
            for (int bi = 0; bi < 2; ++bi) {
                float cacc[8][4];
#pragma unroll
                for (int f = 0; f < 8; ++f) {
                    uint32_t bb[2];
                    bb[0] = movm(h2u(vacc[bi][f][0], vacc[bi][f][1]));   // keys 0-7
                    bb[1] = movm(h2u(vacc[bi][f][2], vacc[bi][f][3]));   // keys 8-15
                    cacc[f][0] = 0.f; cacc[f][1] = 0.f; cacc[f][2] = 0.f; cacc[f][3] = 0.f;
                    mma16816(cacc[f], aP[bi], bb);
                }
                c2a(cacc, ca[bi], false);
            }
            wgemm16x2(ca, wh + 1536, lane, pacc);   // pacc += ctx @ Wp_h
        }
    }

    // ---- x2 = x + attn_out; stash; LN2 in registers -> A2 frags ----
    uint32_t A2[2][4][4];
#pragma unroll
    for (int bi = 0; bi < 2; ++bi) {
        float x2v[8][4];
#pragma unroll
        for (int j = 0; j < 8; ++j) {
            int col = c2 + 8 * j;
            float2 xa = *(const float2*)(xs + row0[bi] * LDF + col);
            float2 xb = *(const float2*)(xs + (row0[bi] + 8) * LDF + col);
            x2v[j][0] = xa.x + pacc[bi][j][0]; x2v[j][1] = xa.y + pacc[bi][j][1];
            x2v[j][2] = xb.x + pacc[bi][j][2]; x2v[j][3] = xb.y + pacc[bi][j][3];
            *(float2*)(xs + row0[bi] * LDF + col)       = make_float2(x2v[j][0], x2v[j][1]);
            *(float2*)(xs + (row0[bi] + 8) * LDF + col) = make_float2(x2v[j][2], x2v[j][3]);
        }
        float s0 = 0.f, q0 = 0.f, s1 = 0.f, q1 = 0.f;
#pragma unroll
        for (int j = 0; j < 8; ++j) {
            s0 += x2v[j][0] + x2v[j][1];
            q0 += x2v[j][0] * x2v[j][0] + x2v[j][1] * x2v[j][1];
            s1 += x2v[j][2] + x2v[j][3];
            q1 += x2v[j][2] * x2v[j][2] + x2v[j][3] * x2v[j][3];
        }
        s0 += __shfl_xor_sync(0xffffffffu, s0, 1); s0 += __shfl_xor_sync(0xffffffffu, s0, 2);
        q0 += __shfl_xor_sync(0xffffffffu, q0, 1); q0 += __shfl_xor_sync(0xffffffffu, q0, 2);
        s1 += __shfl_xor_sync(0xffffffffu, s1, 1); s1 += __shfl_xor_sync(0xffffffffu, s1, 2);
        q1 += __shfl_xor_sync(0xffffffffu, q1, 1); q1 += __shfl_xor_sync(0xffffffffu, q1, 2);
        float mean0 = s0 * (1.f / 64.f), inv0 = rsqrtf(q0 * (1.f / 64.f) - mean0 * mean0 + EPSV);
        float mean1 = s1 * (1.f / 64.f), inv1 = rsqrtf(q1 * (1.f / 64.f) - mean1 * mean1 + EPSV);
        float nv[8][4];
#pragma unroll
        for (int j = 0; j < 8; ++j) {
            int col = c2 + 8 * j;
            float2 gg = __ldg((const float2*)(g2 + col));
            float2 bb = __ldg((const float2*)(be2 + col));
            nv[j][0] = (x2v[j][0] - mean0) * inv0 * gg.x + bb.x;
            nv[j][1] = (x2v[j][1] - mean0) * inv0 * gg.y + bb.y;
            nv[j][2] = (x2v[j][2] - mean1) * inv1 * gg.x + bb.x;
            nv[j][3] = (x2v[j][3] - mean1) * inv1 * gg.y + bb.y;
        }
        c2a(nv, A2[bi], false);
    }

    // ---- FFN: register-resident, shared weight loads ----
    float oacc[2][8][4];
    init16(oacc[0], b2, c2);
    init16(oacc[1], b2, c2);
#pragma unroll 1
    for (int cc = 0; cc < 4; ++cc) {
        float hacc[2][8][4];
        init16(hacc[0], b1 + cc * 64, c2);
        init16(hacc[1], b1 + cc * 64, c2);
        wgemm16x2(A2, gWf + (16 + cc) * 512, lane, hacc);
        uint32_t ha[2][4][4];
        c2a(hacc[0], ha[0], true);          // relu
        c2a(hacc[1], ha[1], true);
        wgemm16x2(ha, gWf + (20 + cc) * 512, lane, oacc);
    }

    // ---- out = x2 + ffn ----
#pragma unroll
    for (int bi = 0; bi < 2; ++bi)
#pragma unroll
        for (int j = 0; j < 8; ++j) {
            int col = c2 + 8 * j;
            float2 xa = *(const float2*)(xs + row0[bi] * LDF + col);
            float2 xb = *(const float2*)(xs + (row0[bi] + 8) * LDF + col);
            *(float2*)(out + (size_t)(g0 + row0[bi]) * 64 + col) =
                make_float2(xa.x + oacc[bi][j][0], xa.y + oacc[bi][j][1]);
            *(float2*)(out + (size_t)(g0 + row0[bi] + 8) * 64 + col) =
                make_float2(xb.x + oacc[bi][j][2], xb.y + oacc[bi][j][3]);
        }
}

extern "C" void kernel_launch(void* const* d_in, const int* in_sizes, int n_in,
                              void* d_out, int out_size) {
    const float* x   = (const float*)d_in[0];
    const float* Wq  = (const float*)d_in[1];
    const float* bq  = (const float*)d_in[2];
    const float* Wk  = (const float*)d_in[3];
    const float* bk  = (const float*)d_in[4];
    const float* Wv  = (const float*)d_in[5];
    const float* bv  = (const float*)d_in[6];
    const float* Wp  = (const float*)d_in[7];
    const float* bp  = (const float*)d_in[8];
    const float* W1  = (const float*)d_in[9];
    const float* b1  = (const float*)d_in[10];
    const float* W2  = (const float*)d_in[11];
    const float* b2  = (const float*)d_in[12];
    const float* g1  = (const float*)d_in[13];
    const float* be1 = (const float*)d_in[14];
    const float* g2  = (const float*)d_in[15];
    const float* be2 = (const float*)d_in[16];
    float* out = (float*)d_out;

    pack_weights<<<24, 256>>>(Wq, Wk, Wv, Wp, W1, W2);

    const int smem_bytes = TOK * LDF * (int)sizeof(float);   // 69632
    cudaFuncSetAttribute(tblock_kernel, cudaFuncAttributeMaxDynamicSharedMemorySize, smem_bytes);

    dim3 grid(Bn * 16 / TOK);   // 1024
    dim3 block(NTH);
    tblock_kernel<<<grid, block, smem_bytes>>>(x, bq, bk, bv, bp, b1, b2,
                                               g1, be1, g2, be2, out);
}